// round 11
// baseline (speedup 1.0000x reference)
#include <cuda_runtime.h>

// v: [8][1024][8][64] f32, w: [1][8][63] f32, out: [8][1024][8][64] f32
// out[n,j,h,d] = A[n,h,a,d] + B[n,h,b,d],  j = a*32+b,  l = c*32+e
//   A = bias @ R,  B = bias @ C
//   R[c,:] = sum_e v[n, c*32+e, :],  C[e,:] = sum_c v[n, c*32+e, :]
//   bias[h,j,k] = w[h, (32 - k + j) mod 63]
//
// ONE persistent kernel, 256 blocks x 256 thr, 2 blocks/SM (all co-resident).
// Phase 1: block (n,c) reads a CONTIGUOUS 64KB chunk (DRAM-optimal), writes
//          complete R[n,c,:] to global scratch. v stays in L2.
// Grid barrier: monotonic counter (replay-safe, no reset).
// Phase 2: block (n,h,q,G) computes C from L2-resident v, matvec, stores its
//          64KB j-half. Stores retire at L2; DRAM drain overlaps next replay.

#define THREADS 256

__device__ float4   g_R4[8 * 32 * 128];   // R[n][c][hd] as float4, 512KB
__device__ unsigned g_ctr;                // barrier counter (monotonic)

__global__ __launch_bounds__(THREADS, 2)
void fused_kernel(const float4* __restrict__ v4,
                  const float*  __restrict__ w,
                  float4* __restrict__ out4) {
    int blk = blockIdx.x;              // 0..255
    int tid = threadIdx.x;

    __shared__ float4 sP[2][128];      // phase-1 partials
    __shared__ float4 sR[32][8], sC[32][8];
    __shared__ float4 sA[32][8], sB[32][8];
    __shared__ float  sb[32][33];
    __shared__ unsigned s_target;

    // ================= Phase 1: R[n][c][:] from contiguous chunk ===========
    {
        int n = blk >> 5;
        int c = blk & 31;
        int eh  = tid >> 7;            // 0..1 : e-half
        int col = tid & 127;           // float4 column 0..127 (warp = 512B row seg)
        const float4* p = v4 + ((size_t)(n * 1024 + c * 32 + eh * 16)) * 128 + col;
        float4 acc = make_float4(0.f, 0.f, 0.f, 0.f);
        #pragma unroll
        for (int i = 0; i < 16; ++i) {
            float4 x = p[i * 128];
            acc.x += x.x; acc.y += x.y; acc.z += x.z; acc.w += x.w;
        }
        sP[eh][col] = acc;
        __syncthreads();
        if (tid < 128) {
            float4 a = sP[0][tid], b = sP[1][tid];
            a.x += b.x; a.y += b.y; a.z += b.z; a.w += b.w;
            g_R4[(n * 32 + c) * 128 + tid] = a;
        }
    }

    // ================= Grid barrier (replay-safe monotonic counter) =========
    __threadfence();                   // release g_R4 writes
    __syncthreads();
    if (tid == 0) {
        unsigned my = atomicAdd(&g_ctr, 1u) + 1u;      // 1-based
        unsigned gen = (my - 1u) / 256u;               // this launch's epoch
        unsigned target = (gen + 1u) * 256u;
        s_target = target;
        while (true) {
            unsigned cur = *(volatile unsigned*)&g_ctr;
            if (cur >= target) break;
            __nanosleep(64);
        }
    }
    __syncthreads();
    __threadfence();                   // acquire peers' g_R4 writes

    // ================= Phase 2: block = (n, h, q, G j-half) =================
    {
        int G = blk & 1;               // j-half owner
        int q = (blk >> 1) & 1;        // d-half: float4 cols [q*8, q*8+8)
        int h = (blk >> 2) & 7;
        int n = blk >> 5;
        int d4 = tid & 7;
        int r  = tid >> 3;             // 0..31

        const float4* base = v4 + ((size_t)n * 1024) * 128 + h * 16 + q * 8 + d4;

        // C[e][d4] = sum_c v[c*32+e]  (L2-resident reads, stride 512B)
        {
            const float4* p = base + (size_t)r * 128;
            float4 acc = make_float4(0.f, 0.f, 0.f, 0.f);
            #pragma unroll
            for (int cc = 0; cc < 32; ++cc) {
                float4 x = p[cc * 32 * 128];
                acc.x += x.x; acc.y += x.y; acc.z += x.z; acc.w += x.w;
            }
            sC[r][d4] = acc;
        }
        // R slice from scratch
        sR[r][d4] = g_R4[(n * 32 + r) * 128 + h * 16 + q * 8 + d4];

        // bias tile
        #pragma unroll
        for (int idx = tid; idx < 1024; idx += THREADS) {
            int j = idx >> 5, k = idx & 31;
            sb[j][k] = w[h * 63 + ((32 - k + j) % 63)];
        }
        __syncthreads();

        // A = bias @ R, B = bias @ C
        {
            float4 accA = make_float4(0.f, 0.f, 0.f, 0.f);
            float4 accB = make_float4(0.f, 0.f, 0.f, 0.f);
            #pragma unroll
            for (int k = 0; k < 32; ++k) {
                float f = sb[r][k];
                float4 x = sR[k][d4];
                float4 y = sC[k][d4];
                accA.x = fmaf(f, x.x, accA.x);
                accA.y = fmaf(f, x.y, accA.y);
                accA.z = fmaf(f, x.z, accA.z);
                accA.w = fmaf(f, x.w, accA.w);
                accB.x = fmaf(f, y.x, accB.x);
                accB.y = fmaf(f, y.y, accB.y);
                accB.z = fmaf(f, y.z, accB.z);
                accB.w = fmaf(f, y.w, accB.w);
            }
            sA[r][d4] = accA;
            sB[r][d4] = accB;
        }
        __syncthreads();

        // store own j-half: j = G*512 + i*32 + r  (b = r invariant, a = G*16+i)
        {
            float4 y = sB[r][d4];
            float4* po = out4 + ((size_t)(n * 1024 + G * 512 + r)) * 128
                              + h * 16 + q * 8 + d4;
            #pragma unroll
            for (int i = 0; i < 16; ++i) {
                float4 x = sA[G * 16 + i][d4];
                x.x += y.x; x.y += y.y; x.z += y.z; x.w += y.w;
                po[(size_t)i * 32 * 128] = x;
            }
        }
    }
}

extern "C" void kernel_launch(void* const* d_in, const int* in_sizes, int n_in,
                              void* d_out, int out_size) {
    const float* v = (const float*)d_in[0];
    const float* w = (const float*)d_in[1];
    if (n_in >= 2 && in_sizes[0] < in_sizes[1]) {
        const float* tmp = v; v = w; w = tmp;
    }

    fused_kernel<<<256, THREADS>>>((const float4*)v, w, (float4*)d_out);
}

// round 12
// speedup vs baseline: 1.3409x; 1.3409x over previous
#include <cuda_runtime.h>

// v: [8][1024][8][64] f32, w: [1][8][63] f32, out: [8][1024][8][64] f32
// out[n,j,h,d] = A[n,h,a,d] + B[n,h,b,d],  j = a*32+b,  l = c*32+e
//   A = bias @ R,  B = bias @ C
//   R[c,d] = sum_e v[n, c*32+e, h, d],  C[e,d] = sum_c v[n, c*32+e, h, d]
//   bias[h,j,k] = w[h, (32 - k + j) mod 63]
//
// Single kernel, 128 blocks = (n, h, d-half), 1024 threads (32 warps/SM),
// 8-deep load chains (regs <= 64, no spill). Every LDG.128 covers whole
// 128B lines (8 consecutive d4 lanes). Two-pass R (contig) / C (strided,
// L1 re-hit), 4-way smem combine, tiny matvec, coalesced store.

#define THREADS 1024

__global__ __launch_bounds__(THREADS, 1)
void fused_kernel(const float4* __restrict__ v4,
                  const float*  __restrict__ w,
                  float4* __restrict__ out4) {
    int blk = blockIdx.x;          // 0..127
    int q = blk & 1;               // d-half: float4 cols [q*8, q*8+8)
    int h = (blk >> 1) & 7;
    int n = blk >> 4;              // 0..7
    int tid = threadIdx.x;

    __shared__ float4 sRp[4][32][8];   // pass-1 partials (eh in 0..3)
    __shared__ float4 sCp[4][32][8];   // pass-2 partials
    __shared__ float4 sR[32][8], sC[32][8];
    __shared__ float4 sA[32][8], sB[32][8];
    __shared__ float  sb[32][33];

    int c  = tid >> 5;        // 0..31 : c (pass1) / e (pass2)
    int eh = (tid >> 3) & 3;  // 0..3  : row sub-group
    int d4 = tid & 7;         // 0..7  : float4 column within the half

    const float4* base = v4 + ((size_t)n * 1024) * 128 + h * 16 + q * 8 + d4;

    // ---- Pass 1: R partials. rows l = c*32 + eh*8 + i (contiguous) ----
    {
        const float4* p = base + (size_t)(c * 32 + eh * 8) * 128;
        float4 acc = make_float4(0.f, 0.f, 0.f, 0.f);
        #pragma unroll
        for (int i = 0; i < 8; ++i) {
            float4 x = p[i * 128];
            acc.x += x.x; acc.y += x.y; acc.z += x.z; acc.w += x.w;
        }
        sRp[eh][c][d4] = acc;
    }

    // ---- Pass 2: C partials. rows l = (eh*8+i)*32 + c (L1 re-hit) ----
    {
        const float4* p = base + (size_t)(eh * 8 * 32 + c) * 128;
        float4 acc = make_float4(0.f, 0.f, 0.f, 0.f);
        #pragma unroll
        for (int i = 0; i < 8; ++i) {
            float4 x = p[i * 32 * 128];
            acc.x += x.x; acc.y += x.y; acc.z += x.z; acc.w += x.w;
        }
        sCp[eh][c][d4] = acc;
    }

    // ---- bias tile (1 entry/thread) ----
    if (tid < 1024) {
        int j = tid >> 5, k = tid & 31;
        sb[j][k] = w[h * 63 + ((32 - k + j) % 63)];
    }
    __syncthreads();

    // ---- combine 4-way partials (512 threads: R half, C half) ----
    if (tid < 512) {
        int which = tid >> 8;          // 0: R, 1: C
        int t = tid & 255;
        int kk = t >> 3, dd = t & 7;
        const float4 (*p)[32][8] = which ? sCp : sRp;
        float4 a = p[0][kk][dd], b = p[1][kk][dd];
        float4 cc = p[2][kk][dd], e = p[3][kk][dd];
        a.x = (a.x + b.x) + (cc.x + e.x);
        a.y = (a.y + b.y) + (cc.y + e.y);
        a.z = (a.z + b.z) + (cc.z + e.z);
        a.w = (a.w + b.w) + (cc.w + e.w);
        (which ? sC : sR)[kk][dd] = a;
    }
    __syncthreads();

    // ---- matvec: A = bias@R (tids 0..255), B = bias@C (tids 256..511) ----
    if (tid < 512) {
        int which = tid >> 8;
        int t = tid & 255;
        int a = t >> 3, dd = t & 7;
        const float4 (*src)[8] = which ? sC : sR;
        float4 acc = make_float4(0.f, 0.f, 0.f, 0.f);
        #pragma unroll
        for (int k = 0; k < 32; ++k) {
            float f = sb[a][k];
            float4 x = src[k][dd];
            acc.x = fmaf(f, x.x, acc.x);
            acc.y = fmaf(f, x.y, acc.y);
            acc.z = fmaf(f, x.z, acc.z);
            acc.w = fmaf(f, x.w, acc.w);
        }
        (which ? sB : sA)[a][dd] = acc;
    }
    __syncthreads();

    // ---- store: j = i*128 + jg; 8 float4 per thread, coalesced ----
    {
        int jg = tid >> 3;             // 0..127
        float4* po = out4 + ((size_t)n * 1024) * 128 + h * 16 + q * 8 + d4;
        #pragma unroll
        for (int i = 0; i < 8; ++i) {
            int j = i * 128 + jg;
            int a = j >> 5, b = j & 31;
            float4 x = sA[a][d4];
            float4 y = sB[b][d4];
            x.x += y.x; x.y += y.y; x.z += y.z; x.w += y.w;
            po[(size_t)j * 128] = x;
        }
    }
}

extern "C" void kernel_launch(void* const* d_in, const int* in_sizes, int n_in,
                              void* d_out, int out_size) {
    const float* v = (const float*)d_in[0];
    const float* w = (const float*)d_in[1];
    if (n_in >= 2 && in_sizes[0] < in_sizes[1]) {
        const float* tmp = v; v = w; w = tmp;
    }

    fused_kernel<<<128, THREADS>>>((const float4*)v, w, (float4*)d_out);
}

// round 14
// speedup vs baseline: 1.4090x; 1.0507x over previous
#include <cuda_runtime.h>
#include <cstdint>

// v: [8][1024][8][64] f32, w: [1][8][63] f32, out: [8][1024][8][64] f32
// out[n,j,h,d] = A[n,h,a,d] + B[n,h,b,d],  j = a*32+b,  l = c*32+e
//   A = bias @ R,  B = bias @ C
//   R[c,d] = sum_e v[n, c*32+e, h, d],  C[e,d] = sum_c v[n, c*32+e, h, d]
//   bias[h,j,k] = w[h, (32 - k + j) mod 63]
//
// R4 skeleton (128 blocks = (n,h,d-half), 512 threads) + cache policy:
//   v loads:  ld.global.nc.L2::cache_hint with evict_last policy (keep v in L2)
//   out store: st.global.cs (evict-first streaming; write-once data)

#define THREADS 512

__device__ __forceinline__ uint64_t mk_evict_last_policy() {
    uint64_t pol;
    asm volatile("createpolicy.fractional.L2::evict_last.b64 %0, 1.0;" : "=l"(pol));
    return pol;
}

__device__ __forceinline__ float4 ldg_keep(const float4* p, uint64_t pol) {
    float4 v;
    asm volatile("ld.global.nc.L2::cache_hint.v4.f32 {%0,%1,%2,%3}, [%4], %5;"
                 : "=f"(v.x), "=f"(v.y), "=f"(v.z), "=f"(v.w)
                 : "l"(p), "l"(pol));
    return v;
}

__global__ __launch_bounds__(THREADS, 1)
void fused_kernel(const float4* __restrict__ v4,
                  const float*  __restrict__ w,
                  float4* __restrict__ out4) {
    int blk = blockIdx.x;          // 0..127
    int q = blk & 1;               // d-half: float4 cols [q*8, q*8+8)
    int h = (blk >> 1) & 7;
    int n = blk >> 4;              // 0..7
    int tid = threadIdx.x;

    __shared__ float4 sRp[2][32][8];   // pass-1 partials (eh split)
    __shared__ float4 sCp[2][32][8];
    __shared__ float4 sR[32][8], sC[32][8];
    __shared__ float4 sA[32][8], sB[32][8];
    __shared__ float  sb[32][33];

    int c  = tid >> 4;        // 0..31 : c (pass1) / e (pass2)
    int eh = (tid >> 3) & 1;  // 0..1  : row sub-group
    int d4 = tid & 7;         // 0..7  : float4 column within the half

    uint64_t pol = mk_evict_last_policy();
    const float4* base = v4 + ((size_t)n * 1024) * 128 + h * 16 + q * 8 + d4;

    // ---- Pass 1: R partials. rows l = c*32 + eh*16 + i (contiguous) ----
    {
        const float4* p = base + (size_t)(c * 32 + eh * 16) * 128;
        float4 acc = make_float4(0.f, 0.f, 0.f, 0.f);
        #pragma unroll
        for (int i = 0; i < 16; ++i) {
            float4 x = ldg_keep(p + i * 128, pol);
            acc.x += x.x; acc.y += x.y; acc.z += x.z; acc.w += x.w;
        }
        sRp[eh][c][d4] = acc;
    }

    // ---- Pass 2: C partials. rows l = (eh*16+i)*32 + c (L1/L2 re-hit) ----
    {
        const float4* p = base + (size_t)(eh * 16 * 32 + c) * 128;
        float4 acc = make_float4(0.f, 0.f, 0.f, 0.f);
        #pragma unroll
        for (int i = 0; i < 16; ++i) {
            float4 x = ldg_keep(p + i * 32 * 128, pol);
            acc.x += x.x; acc.y += x.y; acc.z += x.z; acc.w += x.w;
        }
        sCp[eh][c][d4] = acc;
    }

    // ---- bias tile (2 entries/thread) ----
    #pragma unroll
    for (int idx = tid; idx < 1024; idx += THREADS) {
        int j = idx >> 5, k = idx & 31;
        sb[j][k] = w[h * 63 + ((32 - k + j) % 63)];
    }
    __syncthreads();

    // ---- combine eh-partials (512 threads: R half, C half) ----
    {
        int which = tid >> 8;          // 0: R, 1: C
        int t = tid & 255;
        int kk = t >> 3, dd = t & 7;
        const float4 (*p)[32][8] = which ? sCp : sRp;
        float4 a = p[0][kk][dd], b = p[1][kk][dd];
        a.x += b.x; a.y += b.y; a.z += b.z; a.w += b.w;
        (which ? sC : sR)[kk][dd] = a;
    }
    __syncthreads();

    // ---- matvec: A = bias@R (tids 0..255), B = bias@C (tids 256..511) ----
    {
        int which = tid >> 8;
        int t = tid & 255;
        int a = t >> 3, dd = t & 7;
        const float4 (*src)[8] = which ? sC : sR;
        float4 acc = make_float4(0.f, 0.f, 0.f, 0.f);
        #pragma unroll
        for (int k = 0; k < 32; ++k) {
            float f = sb[a][k];
            float4 x = src[k][dd];
            acc.x = fmaf(f, x.x, acc.x);
            acc.y = fmaf(f, x.y, acc.y);
            acc.z = fmaf(f, x.z, acc.z);
            acc.w = fmaf(f, x.w, acc.w);
        }
        (which ? sB : sA)[a][dd] = acc;
    }
    __syncthreads();

    // ---- store: j = i*64 + jg; streaming (evict-first) ----
    {
        int jg = tid >> 3;             // 0..63
        float4* po = out4 + ((size_t)n * 1024) * 128 + h * 16 + q * 8 + d4;
        #pragma unroll
        for (int i = 0; i < 16; ++i) {
            int j = i * 64 + jg;
            int a = j >> 5, b = j & 31;
            float4 x = sA[a][d4];
            float4 y = sB[b][d4];
            x.x += y.x; x.y += y.y; x.z += y.z; x.w += y.w;
            __stcs(po + (size_t)j * 128, x);
        }
    }
}

extern "C" void kernel_launch(void* const* d_in, const int* in_sizes, int n_in,
                              void* d_out, int out_size) {
    const float* v = (const float*)d_in[0];
    const float* w = (const float*)d_in[1];
    if (n_in >= 2 && in_sizes[0] < in_sizes[1]) {
        const float* tmp = v; v = w; w = tmp;
    }

    fused_kernel<<<128, THREADS>>>((const float4*)v, w, (float4*)d_out);
}